// round 10
// baseline (speedup 1.0000x reference)
#include <cuda_runtime.h>
#include <cuda_fp16.h>

#define NN   100000
#define DIMC 64
#define HH   4
#define EMAX 1600000

// Scratch (allocation-free rule: __device__ globals)
__device__ __half g_qh[NN * DIMC];
__device__ __half g_kh[NN * DIMC];
__device__ __half g_vh[NN * DIMC];
__device__ float  g_acc[NN * DIMC];   // normalized attention output (gather)

// CSR scratch
__device__ int g_cnt[NN];         // counts, then fill cursors
__device__ int g_ptr[NN + 1];
__device__ int g_ssrc[EMAX];      // src ids sorted by dst

// Pre-split, fragment-ordered W images (hi/lo tf32), one per matrix
// (0=Wq, 1=Wk, 2=Wv, 3=Wo). Layout: [(nt*8 + ks)*32 + lane] holds the uint2
// B-fragment {W[c][k0], W[c][k0+4]} with c = nt*8 + lane/4, k0 = ks*8 + lane%4.
__device__ uint2 g_Bhi[4][2048];
__device__ uint2 g_Blo[4][2048];

__device__ __forceinline__ unsigned f2tf32(float x) {
    unsigned r;
    asm("cvt.rna.tf32.f32 %0, %1;" : "=r"(r) : "f"(x));
    return r;
}

// ---------------------------------------------------------------------------
// Pack kernel: split each W into tf32 hi/lo and store in B-fragment order.
// ---------------------------------------------------------------------------
__global__ void pack_kernel(const float* __restrict__ Wq,
                            const float* __restrict__ Wk,
                            const float* __restrict__ Wv,
                            const float* __restrict__ Wo)
{
    int m = blockIdx.x;
    const float* W = (m == 0) ? Wq : (m == 1) ? Wk : (m == 2) ? Wv : Wo;
#pragma unroll
    for (int i = 0; i < 8; i++) {
        int idx  = threadIdx.x + i * 256;     // 0..2047
        int lane = idx & 31;
        int ks   = (idx >> 5) & 7;
        int nt   = idx >> 8;
        int c    = nt * 8 + (lane >> 2);
        int k0   = ks * 8 + (lane & 3);
        float w0 = W[c * DIMC + k0];
        float w1 = W[c * DIMC + k0 + 4];
        uint2 h, l;
        h.x = f2tf32(w0); h.y = f2tf32(w1);
        l.x = f2tf32(w0 - __uint_as_float(h.x));
        l.y = f2tf32(w1 - __uint_as_float(h.y));
        g_Bhi[m][idx] = h;
        g_Blo[m][idx] = l;
    }
}

// ---------------------------------------------------------------------------
// CSR build: zero counts -> histogram -> scan -> scatter
// ---------------------------------------------------------------------------
__global__ void hist_zero_kernel() {
    int i = blockIdx.x * blockDim.x + threadIdx.x;
    if (i < NN) g_cnt[i] = 0;
}

__global__ void hist_kernel(const int* __restrict__ dst, int E) {
    int i = blockIdx.x * blockDim.x + threadIdx.x;
    int stride = gridDim.x * blockDim.x;
    for (int e = i; e < E; e += stride) atomicAdd(&g_cnt[dst[e]], 1);
}

// Single-block exclusive scan of g_cnt[0..NN) -> g_ptr; g_cnt becomes cursor.
__global__ __launch_bounds__(1024) void scan_kernel(int E) {
    __shared__ int ssum[1024];
    const int CH = (NN + 1023) / 1024;   // 98
    int t  = threadIdx.x;
    int lo = t * CH, hi = min(lo + CH, NN);
    int s = 0;
    for (int i = lo; i < hi; i++) s += g_cnt[i];
    ssum[t] = s;
    __syncthreads();
    for (int off = 1; off < 1024; off <<= 1) {
        int v = (t >= off) ? ssum[t - off] : 0;
        __syncthreads();
        ssum[t] += v;
        __syncthreads();
    }
    int run = (t > 0) ? ssum[t - 1] : 0;
    for (int i = lo; i < hi; i++) {
        int c = g_cnt[i];
        g_ptr[i] = run;
        g_cnt[i] = run;   // fill cursor
        run += c;
    }
    if (t == 0) g_ptr[NN] = E;
}

__global__ void scatter_kernel(const int* __restrict__ src,
                               const int* __restrict__ dst, int E) {
    int i = blockIdx.x * blockDim.x + threadIdx.x;
    int stride = gridDim.x * blockDim.x;
    for (int e = i; e < E; e += stride) {
        int pos = atomicAdd(&g_cnt[dst[e]], 1);
        g_ssrc[pos] = src[e];
    }
}

// ---------------------------------------------------------------------------
// Gather kernel: one warp per dst node. Processes 2 edges per iteration
// (half-warp h handles edge j+h): each lane loads k & v fragments of its
// half's edge, butterfly-reduces the per-head dot, exp, and accumulates
// acc += ex*v and den in registers. Epilogue folds halves, normalizes, and
// stores the final per-node attention output once. NO atomics anywhere.
// ---------------------------------------------------------------------------
__global__ __launch_bounds__(256) void gather_kernel() {
    int gw   = (blockIdx.x * blockDim.x + threadIdx.x) >> 5;
    int lane = threadIdx.x & 31;
    if (gw >= NN) return;
    int start = g_ptr[gw], end = g_ptr[gw + 1];

    int sub = lane & 15;
    int h   = lane >> 4;

    // q fragment for my sub (both halves load same row fragment — broadcast)
    uint2 qr = *(const uint2*)(g_qh + (size_t)gw * DIMC + sub * 4);
    float2 q0 = __half22float2(*(__half2*)&qr.x);
    float2 q1 = __half22float2(*(__half2*)&qr.y);

    float a0 = 0.f, a1 = 0.f, a2 = 0.f, a3 = 0.f;   // v accum (4 dims of sub)
    float den = 0.f;                                 // valid at (sub&3)==0

    for (int base = start; base < end; base += 32) {
        int cnt = min(end - base, 32);
        int s_l = (lane < cnt) ? g_ssrc[base + lane] : 0;
        for (int j = 0; j < cnt; j += 2) {
            int  idx   = j + h;
            bool valid = idx < cnt;
            int  s     = __shfl_sync(0xffffffffu, s_l, idx & 31);

            uint2 kr = *(const uint2*)(g_kh + (size_t)s * DIMC + sub * 4);
            float2 k0 = __half22float2(*(__half2*)&kr.x);
            float2 k1 = __half22float2(*(__half2*)&kr.y);
            float p = q0.x * k0.x + q0.y * k0.y + q1.x * k1.x + q1.y * k1.y;
            p += __shfl_xor_sync(0xffffffffu, p, 1);
            p += __shfl_xor_sync(0xffffffffu, p, 2);
            float ex = valid ? __expf(p * 0.25f) : 0.f;
            if ((sub & 3) == 0) den += ex;

            uint2 vr = *(const uint2*)(g_vh + (size_t)s * DIMC + sub * 4);
            float2 v0 = __half22float2(*(__half2*)&vr.x);
            float2 v1 = __half22float2(*(__half2*)&vr.y);
            a0 += ex * v0.x; a1 += ex * v0.y;
            a2 += ex * v1.x; a3 += ex * v1.y;
        }
    }

    // fold the two halves
    a0  += __shfl_down_sync(0xffffffffu, a0, 16);
    a1  += __shfl_down_sync(0xffffffffu, a1, 16);
    a2  += __shfl_down_sync(0xffffffffu, a2, 16);
    a3  += __shfl_down_sync(0xffffffffu, a3, 16);
    den += __shfl_down_sync(0xffffffffu, den, 16);
    // broadcast head denominator within each 4-lane group (head base lane)
    float dh  = __shfl_sync(0xffffffffu, den, sub & 12);
    if (lane < 16) {
        float inv = (dh > 0.f) ? (1.f / dh) : 0.f;
        float4 o  = make_float4(a0 * inv, a1 * inv, a2 * inv, a3 * inv);
        *(float4*)(g_acc + (size_t)gw * DIMC + sub * 4) = o;
    }
}

// ---------------------------------------------------------------------------
// Tensor-core GEMM (3xTF32): out[node] = X[node] @ W^T + b, fp32 accuracy.
// ---------------------------------------------------------------------------
__device__ __forceinline__ void mma_tf32(float* c, const unsigned* a,
                                         unsigned b0, unsigned b1) {
    asm volatile(
        "mma.sync.aligned.m16n8k8.row.col.f32.tf32.tf32.f32 "
        "{%0,%1,%2,%3},{%4,%5,%6,%7},{%8,%9},{%0,%1,%2,%3};"
        : "+f"(c[0]), "+f"(c[1]), "+f"(c[2]), "+f"(c[3])
        : "r"(a[0]), "r"(a[1]), "r"(a[2]), "r"(a[3]), "r"(b0), "r"(b1));
}

template <bool OUT_HALF>
__device__ __forceinline__ void gemm_tc(const float* __restrict__ X,
                                        int wsel,
                                        const float* __restrict__ bias,
                                        void* __restrict__ out)
{
    __shared__ float sX[64 * 64];     // 16 KB fp32 tile (later reused for C)
    __shared__ uint2 sBhi[2048];      // 16 KB packed tf32-hi fragments
    __shared__ uint2 sBlo[2048];      // 16 KB packed tf32-lo fragments

    int tid  = threadIdx.x;
    int base = blockIdx.x * 64;

#pragma unroll
    for (int i = 0; i < 8; i++) {
        int idx = tid + i * 256;
        sBhi[idx] = g_Bhi[wsel][idx];
        sBlo[idx] = g_Blo[wsel][idx];
    }

#pragma unroll
    for (int i = 0; i < 4; i++) {
        int idx  = tid + i * 256;
        int row  = idx >> 4;
        int k4   = idx & 15;
        int node = base + row;
        float4 xv = make_float4(0.f, 0.f, 0.f, 0.f);
        if (node < NN) xv = ((const float4*)(X + (size_t)node * DIMC))[k4];
        ((float4*)sX)[row * 16 + (k4 ^ (row & 15))] = xv;
    }
    __syncthreads();

    int lane = tid & 31, warp = tid >> 5;
    int rowg = warp >> 1;
    int colh = warp & 1;
    int gid  = lane >> 2;
    int tig  = lane & 3;
    int r0   = rowg * 16 + gid;
    int r1   = r0 + 8;

    float acc[4][4];
#pragma unroll
    for (int n = 0; n < 4; n++)
#pragma unroll
        for (int j = 0; j < 4; j++) acc[n][j] = 0.f;

#pragma unroll
    for (int ks = 0; ks < 8; ks++) {
        int g0 = 2 * ks;
        int g1 = 2 * ks + 1;
        float a0f = sX[(r0 * 16 + (g0 ^ (r0 & 15))) * 4 + tig];
        float a1f = sX[(r1 * 16 + (g0 ^ (r1 & 15))) * 4 + tig];
        float a2f = sX[(r0 * 16 + (g1 ^ (r0 & 15))) * 4 + tig];
        float a3f = sX[(r1 * 16 + (g1 ^ (r1 & 15))) * 4 + tig];
        unsigned ah[4], al[4];
        ah[0] = f2tf32(a0f); al[0] = f2tf32(a0f - __uint_as_float(ah[0]));
        ah[1] = f2tf32(a1f); al[1] = f2tf32(a1f - __uint_as_float(ah[1]));
        ah[2] = f2tf32(a2f); al[2] = f2tf32(a2f - __uint_as_float(ah[2]));
        ah[3] = f2tf32(a3f); al[3] = f2tf32(a3f - __uint_as_float(ah[3]));
#pragma unroll
        for (int n = 0; n < 4; n++) {
            int nt = colh * 4 + n;
            int bi = (nt * 8 + ks) * 32 + lane;
            uint2 bh = sBhi[bi];
            uint2 bl = sBlo[bi];
            mma_tf32(acc[n], ah, bh.x, bh.y);
            mma_tf32(acc[n], al, bh.x, bh.y);
            mma_tf32(acc[n], ah, bl.x, bl.y);
        }
    }

    __syncthreads();
#pragma unroll
    for (int n = 0; n < 4; n++) {
        int col = (colh * 4 + n) * 8 + 2 * tig;
        int g   = col >> 2;
        int o   = col & 3;
        sX[(r0 * 16 + (g ^ (r0 & 15))) * 4 + o]     = acc[n][0];
        sX[(r0 * 16 + (g ^ (r0 & 15))) * 4 + o + 1] = acc[n][1];
        sX[(r1 * 16 + (g ^ (r1 & 15))) * 4 + o]     = acc[n][2];
        sX[(r1 * 16 + (g ^ (r1 & 15))) * 4 + o + 1] = acc[n][3];
    }
    __syncthreads();

#pragma unroll
    for (int i = 0; i < 4; i++) {
        int idx  = tid + i * 256;
        int row  = idx >> 4;
        int k4   = idx & 15;
        int node = base + row;
        if (node >= NN) continue;
        float4 v  = ((const float4*)sX)[row * 16 + (k4 ^ (row & 15))];
        float4 bb = ((const float4*)bias)[k4];
        v.x += bb.x; v.y += bb.y; v.z += bb.z; v.w += bb.w;
        if (OUT_HALF) {
            __half2 h0 = __float22half2_rn(make_float2(v.x, v.y));
            __half2 h1 = __float22half2_rn(make_float2(v.z, v.w));
            uint2 pk;
            pk.x = *(unsigned*)&h0;
            pk.y = *(unsigned*)&h1;
            *(uint2*)((__half*)out + (size_t)node * DIMC + k4 * 4) = pk;
        } else {
            *(float4*)((float*)out + (size_t)node * DIMC + k4 * 4) = v;
        }
    }
}

__global__ __launch_bounds__(256)
void proj_kernel(const float* __restrict__ query,
                 const float* __restrict__ key,
                 const float* __restrict__ value,
                 const float* __restrict__ bq,
                 const float* __restrict__ bk,
                 const float* __restrict__ bv)
{
    int m = blockIdx.y;
    if (m == 0)      gemm_tc<true>(query, 0, bq, g_qh);
    else if (m == 1) gemm_tc<true>(key,   1, bk, g_kh);
    else             gemm_tc<true>(value, 2, bv, g_vh);
}

__global__ __launch_bounds__(256)
void final_kernel(const float* __restrict__ bo,
                  float* __restrict__ out)
{
    gemm_tc<false>(g_acc, 3, bo, out);
}

// ---------------------------------------------------------------------------
extern "C" void kernel_launch(void* const* d_in, const int* in_sizes, int n_in,
                              void* d_out, int out_size)
{
    const float* query = (const float*)d_in[0];
    const float* key   = (const float*)d_in[1];
    const float* value = (const float*)d_in[2];
    const int*   src   = (const int*)d_in[3];
    const int*   dst   = (const int*)d_in[4];
    const float* bq = (const float*)d_in[6];
    const float* bk = (const float*)d_in[8];
    const float* bv = (const float*)d_in[10];
    const float* bo = (const float*)d_in[12];
    const float* Wq = (const float*)d_in[5];
    const float* Wk = (const float*)d_in[7];
    const float* Wv = (const float*)d_in[9];
    const float* Wo = (const float*)d_in[11];
    int E = in_sizes[3];
    if (E > EMAX) E = EMAX;

    pack_kernel<<<4, 256>>>(Wq, Wk, Wv, Wo);

    // CSR build
    hist_zero_kernel<<<(NN + 255) / 256, 256>>>();
    hist_kernel<<<1024, 256>>>(dst, E);
    scan_kernel<<<1, 1024>>>(E);
    scatter_kernel<<<1024, 256>>>(src, dst, E);

    // Projections
    dim3 pg((NN + 63) / 64, 3);
    proj_kernel<<<pg, 256>>>(query, key, value, bq, bk, bv);

    // Attention (register-accumulated, atomic-free)
    gather_kernel<<<(NN * 32 + 255) / 256, 256>>>();

    // Output projection
    final_kernel<<<(NN + 63) / 64, 256>>>(bo, (float*)d_out);
}

// round 12
// speedup vs baseline: 1.7469x; 1.7469x over previous
#include <cuda_runtime.h>
#include <cuda_fp16.h>

#define NN   100000
#define DIMC 64
#define HH   4
#define EMAX 1600000
#define NB   ((NN + 255) / 256)   // 391 scan blocks

// Scratch (allocation-free rule: __device__ globals)
__device__ __half g_qh[NN * DIMC];
__device__ __half g_kh[NN * DIMC];
__device__ __half g_vh[NN * DIMC];
__device__ float  g_acc[NN * DIMC];   // normalized attention output (gather)

// CSR scratch
__device__ int g_cnt[NN];         // counts, then fill cursors
__device__ int g_ptr[NN + 1];
__device__ int g_ssrc[EMAX];      // src ids sorted by dst
__device__ int g_blk[NB];         // per-block totals for the scan

// Pre-split, fragment-ordered W images (hi/lo tf32), one per matrix
// (0=Wq, 1=Wk, 2=Wv, 3=Wo). Layout: [(nt*8 + ks)*32 + lane] holds the uint2
// B-fragment {W[c][k0], W[c][k0+4]} with c = nt*8 + lane/4, k0 = ks*8 + lane%4.
__device__ uint2 g_Bhi[4][2048];
__device__ uint2 g_Blo[4][2048];

__device__ __forceinline__ unsigned f2tf32(float x) {
    unsigned r;
    asm("cvt.rna.tf32.f32 %0, %1;" : "=r"(r) : "f"(x));
    return r;
}

// ---------------------------------------------------------------------------
// Pack kernel: split each W into tf32 hi/lo and store in B-fragment order.
// ---------------------------------------------------------------------------
__global__ void pack_kernel(const float* __restrict__ Wq,
                            const float* __restrict__ Wk,
                            const float* __restrict__ Wv,
                            const float* __restrict__ Wo)
{
    int m = blockIdx.x;
    const float* W = (m == 0) ? Wq : (m == 1) ? Wk : (m == 2) ? Wv : Wo;
#pragma unroll
    for (int i = 0; i < 8; i++) {
        int idx  = threadIdx.x + i * 256;     // 0..2047
        int lane = idx & 31;
        int ks   = (idx >> 5) & 7;
        int nt   = idx >> 8;
        int c    = nt * 8 + (lane >> 2);
        int k0   = ks * 8 + (lane & 3);
        float w0 = W[c * DIMC + k0];
        float w1 = W[c * DIMC + k0 + 4];
        uint2 h, l;
        h.x = f2tf32(w0); h.y = f2tf32(w1);
        l.x = f2tf32(w0 - __uint_as_float(h.x));
        l.y = f2tf32(w1 - __uint_as_float(h.y));
        g_Bhi[m][idx] = h;
        g_Blo[m][idx] = l;
    }
}

// ---------------------------------------------------------------------------
// CSR build: zero counts -> histogram -> 3-phase parallel scan -> scatter
// ---------------------------------------------------------------------------
__global__ void hist_zero_kernel() {
    int i = blockIdx.x * blockDim.x + threadIdx.x;
    if (i < NN) g_cnt[i] = 0;
}

__global__ void hist_kernel(const int* __restrict__ dst, int E) {
    int i = blockIdx.x * blockDim.x + threadIdx.x;
    int stride = gridDim.x * blockDim.x;
    for (int e = i; e < E; e += stride) atomicAdd(&g_cnt[dst[e]], 1);
}

// Phase 1: per-block exclusive scan of 256 counts; local prefix -> g_ptr,
// block total -> g_blk.
__global__ __launch_bounds__(256) void scan1_kernel() {
    __shared__ int sh[256];
    int t = threadIdx.x;
    int i = blockIdx.x * 256 + t;
    int v = (i < NN) ? g_cnt[i] : 0;
    sh[t] = v;
    __syncthreads();
    // Hillis-Steele inclusive scan
#pragma unroll
    for (int off = 1; off < 256; off <<= 1) {
        int a = (t >= off) ? sh[t - off] : 0;
        __syncthreads();
        sh[t] += a;
        __syncthreads();
    }
    if (i < NN) g_ptr[i] = sh[t] - v;          // exclusive local prefix
    if (t == 255) g_blk[blockIdx.x] = sh[255]; // block total
}

// Phase 2: single block scans the NB block totals (exclusive).
__global__ __launch_bounds__(512) void scan2_kernel() {
    __shared__ int sh[512];
    int t = threadIdx.x;
    int v = (t < NB) ? g_blk[t] : 0;
    sh[t] = v;
    __syncthreads();
#pragma unroll
    for (int off = 1; off < 512; off <<= 1) {
        int a = (t >= off) ? sh[t - off] : 0;
        __syncthreads();
        sh[t] += a;
        __syncthreads();
    }
    if (t < NB) g_blk[t] = sh[t] - v;          // exclusive block offset
}

// Phase 3: add block offsets; init cursor; set sentinel.
__global__ __launch_bounds__(256) void scan3_kernel(int E) {
    int i = blockIdx.x * 256 + threadIdx.x;
    if (i < NN) {
        int p = g_ptr[i] + g_blk[blockIdx.x];
        g_ptr[i] = p;
        g_cnt[i] = p;   // fill cursor
    }
    if (i == 0) g_ptr[NN] = E;
}

__global__ void scatter_kernel(const int* __restrict__ src,
                               const int* __restrict__ dst, int E) {
    int i = blockIdx.x * blockDim.x + threadIdx.x;
    int stride = gridDim.x * blockDim.x;
    for (int e = i; e < E; e += stride) {
        int pos = atomicAdd(&g_cnt[dst[e]], 1);
        g_ssrc[pos] = src[e];
    }
}

// ---------------------------------------------------------------------------
// Gather kernel: one warp per dst node. Processes 2 edges per iteration
// (half-warp h handles edge j+h): each lane loads k & v fragments of its
// half's edge, butterfly-reduces the per-head dot, exp, and accumulates
// acc += ex*v and den in registers. Epilogue folds halves, normalizes, and
// stores the final per-node attention output once. NO atomics anywhere.
// ---------------------------------------------------------------------------
__global__ __launch_bounds__(256) void gather_kernel() {
    int gw   = (blockIdx.x * blockDim.x + threadIdx.x) >> 5;
    int lane = threadIdx.x & 31;
    if (gw >= NN) return;
    int start = g_ptr[gw], end = g_ptr[gw + 1];

    int sub = lane & 15;
    int h   = lane >> 4;

    // q fragment for my sub (both halves load same row fragment — broadcast)
    uint2 qr = *(const uint2*)(g_qh + (size_t)gw * DIMC + sub * 4);
    float2 q0 = __half22float2(*(__half2*)&qr.x);
    float2 q1 = __half22float2(*(__half2*)&qr.y);

    float a0 = 0.f, a1 = 0.f, a2 = 0.f, a3 = 0.f;   // v accum (4 dims of sub)
    float den = 0.f;                                 // valid at (sub&3)==0

    for (int base = start; base < end; base += 32) {
        int cnt = min(end - base, 32);
        int s_l = (lane < cnt) ? g_ssrc[base + lane] : 0;
        for (int j = 0; j < cnt; j += 2) {
            int  idx   = j + h;
            bool valid = idx < cnt;
            int  s     = __shfl_sync(0xffffffffu, s_l, idx & 31);

            uint2 kr = *(const uint2*)(g_kh + (size_t)s * DIMC + sub * 4);
            float2 k0 = __half22float2(*(__half2*)&kr.x);
            float2 k1 = __half22float2(*(__half2*)&kr.y);
            float p = q0.x * k0.x + q0.y * k0.y + q1.x * k1.x + q1.y * k1.y;
            p += __shfl_xor_sync(0xffffffffu, p, 1);
            p += __shfl_xor_sync(0xffffffffu, p, 2);
            float ex = valid ? __expf(p * 0.25f) : 0.f;
            if ((sub & 3) == 0) den += ex;

            uint2 vr = *(const uint2*)(g_vh + (size_t)s * DIMC + sub * 4);
            float2 v0 = __half22float2(*(__half2*)&vr.x);
            float2 v1 = __half22float2(*(__half2*)&vr.y);
            a0 += ex * v0.x; a1 += ex * v0.y;
            a2 += ex * v1.x; a3 += ex * v1.y;
        }
    }

    // fold the two halves
    a0  += __shfl_down_sync(0xffffffffu, a0, 16);
    a1  += __shfl_down_sync(0xffffffffu, a1, 16);
    a2  += __shfl_down_sync(0xffffffffu, a2, 16);
    a3  += __shfl_down_sync(0xffffffffu, a3, 16);
    den += __shfl_down_sync(0xffffffffu, den, 16);
    // broadcast head denominator within each 4-lane group (head base lane)
    float dh  = __shfl_sync(0xffffffffu, den, sub & 12);
    if (lane < 16) {
        float inv = (dh > 0.f) ? (1.f / dh) : 0.f;
        float4 o  = make_float4(a0 * inv, a1 * inv, a2 * inv, a3 * inv);
        *(float4*)(g_acc + (size_t)gw * DIMC + sub * 4) = o;
    }
}

// ---------------------------------------------------------------------------
// Tensor-core GEMM (3xTF32): out[node] = X[node] @ W^T + b, fp32 accuracy.
// ---------------------------------------------------------------------------
__device__ __forceinline__ void mma_tf32(float* c, const unsigned* a,
                                         unsigned b0, unsigned b1) {
    asm volatile(
        "mma.sync.aligned.m16n8k8.row.col.f32.tf32.tf32.f32 "
        "{%0,%1,%2,%3},{%4,%5,%6,%7},{%8,%9},{%0,%1,%2,%3};"
        : "+f"(c[0]), "+f"(c[1]), "+f"(c[2]), "+f"(c[3])
        : "r"(a[0]), "r"(a[1]), "r"(a[2]), "r"(a[3]), "r"(b0), "r"(b1));
}

template <bool OUT_HALF>
__device__ __forceinline__ void gemm_tc(const float* __restrict__ X,
                                        int wsel,
                                        const float* __restrict__ bias,
                                        void* __restrict__ out)
{
    __shared__ float sX[64 * 64];     // 16 KB fp32 tile (later reused for C)
    __shared__ uint2 sBhi[2048];      // 16 KB packed tf32-hi fragments
    __shared__ uint2 sBlo[2048];      // 16 KB packed tf32-lo fragments

    int tid  = threadIdx.x;
    int base = blockIdx.x * 64;

#pragma unroll
    for (int i = 0; i < 8; i++) {
        int idx = tid + i * 256;
        sBhi[idx] = g_Bhi[wsel][idx];
        sBlo[idx] = g_Blo[wsel][idx];
    }

#pragma unroll
    for (int i = 0; i < 4; i++) {
        int idx  = tid + i * 256;
        int row  = idx >> 4;
        int k4   = idx & 15;
        int node = base + row;
        float4 xv = make_float4(0.f, 0.f, 0.f, 0.f);
        if (node < NN) xv = ((const float4*)(X + (size_t)node * DIMC))[k4];
        ((float4*)sX)[row * 16 + (k4 ^ (row & 15))] = xv;
    }
    __syncthreads();

    int lane = tid & 31, warp = tid >> 5;
    int rowg = warp >> 1;
    int colh = warp & 1;
    int gid  = lane >> 2;
    int tig  = lane & 3;
    int r0   = rowg * 16 + gid;
    int r1   = r0 + 8;

    float acc[4][4];
#pragma unroll
    for (int n = 0; n < 4; n++)
#pragma unroll
        for (int j = 0; j < 4; j++) acc[n][j] = 0.f;

#pragma unroll
    for (int ks = 0; ks < 8; ks++) {
        int g0 = 2 * ks;
        int g1 = 2 * ks + 1;
        float a0f = sX[(r0 * 16 + (g0 ^ (r0 & 15))) * 4 + tig];
        float a1f = sX[(r1 * 16 + (g0 ^ (r1 & 15))) * 4 + tig];
        float a2f = sX[(r0 * 16 + (g1 ^ (r0 & 15))) * 4 + tig];
        float a3f = sX[(r1 * 16 + (g1 ^ (r1 & 15))) * 4 + tig];
        unsigned ah[4], al[4];
        ah[0] = f2tf32(a0f); al[0] = f2tf32(a0f - __uint_as_float(ah[0]));
        ah[1] = f2tf32(a1f); al[1] = f2tf32(a1f - __uint_as_float(ah[1]));
        ah[2] = f2tf32(a2f); al[2] = f2tf32(a2f - __uint_as_float(ah[2]));
        ah[3] = f2tf32(a3f); al[3] = f2tf32(a3f - __uint_as_float(ah[3]));
#pragma unroll
        for (int n = 0; n < 4; n++) {
            int nt = colh * 4 + n;
            int bi = (nt * 8 + ks) * 32 + lane;
            uint2 bh = sBhi[bi];
            uint2 bl = sBlo[bi];
            mma_tf32(acc[n], ah, bh.x, bh.y);
            mma_tf32(acc[n], al, bh.x, bh.y);
            mma_tf32(acc[n], ah, bl.x, bl.y);
        }
    }

    __syncthreads();
#pragma unroll
    for (int n = 0; n < 4; n++) {
        int col = (colh * 4 + n) * 8 + 2 * tig;
        int g   = col >> 2;
        int o   = col & 3;
        sX[(r0 * 16 + (g ^ (r0 & 15))) * 4 + o]     = acc[n][0];
        sX[(r0 * 16 + (g ^ (r0 & 15))) * 4 + o + 1] = acc[n][1];
        sX[(r1 * 16 + (g ^ (r1 & 15))) * 4 + o]     = acc[n][2];
        sX[(r1 * 16 + (g ^ (r1 & 15))) * 4 + o + 1] = acc[n][3];
    }
    __syncthreads();

#pragma unroll
    for (int i = 0; i < 4; i++) {
        int idx  = tid + i * 256;
        int row  = idx >> 4;
        int k4   = idx & 15;
        int node = base + row;
        if (node >= NN) continue;
        float4 v  = ((const float4*)sX)[row * 16 + (k4 ^ (row & 15))];
        float4 bb = ((const float4*)bias)[k4];
        v.x += bb.x; v.y += bb.y; v.z += bb.z; v.w += bb.w;
        if (OUT_HALF) {
            __half2 h0 = __float22half2_rn(make_float2(v.x, v.y));
            __half2 h1 = __float22half2_rn(make_float2(v.z, v.w));
            uint2 pk;
            pk.x = *(unsigned*)&h0;
            pk.y = *(unsigned*)&h1;
            *(uint2*)((__half*)out + (size_t)node * DIMC + k4 * 4) = pk;
        } else {
            *(float4*)((float*)out + (size_t)node * DIMC + k4 * 4) = v;
        }
    }
}

__global__ __launch_bounds__(256)
void proj_kernel(const float* __restrict__ query,
                 const float* __restrict__ key,
                 const float* __restrict__ value,
                 const float* __restrict__ bq,
                 const float* __restrict__ bk,
                 const float* __restrict__ bv)
{
    int m = blockIdx.y;
    if (m == 0)      gemm_tc<true>(query, 0, bq, g_qh);
    else if (m == 1) gemm_tc<true>(key,   1, bk, g_kh);
    else             gemm_tc<true>(value, 2, bv, g_vh);
}

__global__ __launch_bounds__(256)
void final_kernel(const float* __restrict__ bo,
                  float* __restrict__ out)
{
    gemm_tc<false>(g_acc, 3, bo, out);
}

// ---------------------------------------------------------------------------
extern "C" void kernel_launch(void* const* d_in, const int* in_sizes, int n_in,
                              void* d_out, int out_size)
{
    const float* query = (const float*)d_in[0];
    const float* key   = (const float*)d_in[1];
    const float* value = (const float*)d_in[2];
    const int*   src   = (const int*)d_in[3];
    const int*   dst   = (const int*)d_in[4];
    const float* Wq = (const float*)d_in[5];  const float* bq = (const float*)d_in[6];
    const float* Wk = (const float*)d_in[7];  const float* bk = (const float*)d_in[8];
    const float* Wv = (const float*)d_in[9];  const float* bv = (const float*)d_in[10];
    const float* Wo = (const float*)d_in[11]; const float* bo = (const float*)d_in[12];
    int E = in_sizes[3];
    if (E > EMAX) E = EMAX;

    pack_kernel<<<4, 256>>>(Wq, Wk, Wv, Wo);

    // CSR build (parallel scan)
    hist_zero_kernel<<<NB, 256>>>();
    hist_kernel<<<1024, 256>>>(dst, E);
    scan1_kernel<<<NB, 256>>>();
    scan2_kernel<<<1, 512>>>();
    scan3_kernel<<<NB, 256>>>(E);
    scatter_kernel<<<1024, 256>>>(src, dst, E);

    // Projections
    dim3 pg((NN + 63) / 64, 3);
    proj_kernel<<<pg, 256>>>(query, key, value, bq, bk, bv);

    // Attention (register-accumulated, atomic-free)
    gather_kernel<<<(NN * 32 + 255) / 256, 256>>>();

    // Output projection
    final_kernel<<<(NN + 63) / 64, 256>>>(bo, (float*)d_out);
}

// round 14
// speedup vs baseline: 1.7872x; 1.0231x over previous
#include <cuda_runtime.h>
#include <cuda_fp16.h>

#define NN   100000
#define DIMC 64
#define HH   4
#define EMAX 1600000
#define NB   ((NN + 255) / 256)   // 391 scan blocks

// Scratch (allocation-free rule: __device__ globals)
__device__ __half g_qh[NN * DIMC];
__device__ __half g_kh[NN * DIMC];
__device__ __half g_vh[NN * DIMC];
__device__ float  g_acc[NN * DIMC];   // normalized attention output (gather)

// CSR scratch
__device__ int g_cnt[NN];         // counts, then fill cursors
__device__ int g_ptr[NN + 1];
__device__ int g_ssrc[EMAX];      // src ids sorted by dst
__device__ int g_blk[NB];         // per-block totals for the scan

// Pre-split, fragment-ordered W images (hi/lo tf32), one per matrix
// (0=Wq, 1=Wk, 2=Wv, 3=Wo). Layout: [(nt*8 + ks)*32 + lane] holds the uint2
// B-fragment {W[c][k0], W[c][k0+4]} with c = nt*8 + lane/4, k0 = ks*8 + lane%4.
__device__ uint2 g_Bhi[4][2048];
__device__ uint2 g_Blo[4][2048];

__device__ __forceinline__ unsigned f2tf32(float x) {
    unsigned r;
    asm("cvt.rna.tf32.f32 %0, %1;" : "=r"(r) : "f"(x));
    return r;
}

// ---------------------------------------------------------------------------
// Pack kernel: split each W into tf32 hi/lo and store in B-fragment order.
// ---------------------------------------------------------------------------
__global__ void pack_kernel(const float* __restrict__ Wq,
                            const float* __restrict__ Wk,
                            const float* __restrict__ Wv,
                            const float* __restrict__ Wo)
{
    int m = blockIdx.x;
    const float* W = (m == 0) ? Wq : (m == 1) ? Wk : (m == 2) ? Wv : Wo;
#pragma unroll
    for (int i = 0; i < 8; i++) {
        int idx  = threadIdx.x + i * 256;     // 0..2047
        int lane = idx & 31;
        int ks   = (idx >> 5) & 7;
        int nt   = idx >> 8;
        int c    = nt * 8 + (lane >> 2);
        int k0   = ks * 8 + (lane & 3);
        float w0 = W[c * DIMC + k0];
        float w1 = W[c * DIMC + k0 + 4];
        uint2 h, l;
        h.x = f2tf32(w0); h.y = f2tf32(w1);
        l.x = f2tf32(w0 - __uint_as_float(h.x));
        l.y = f2tf32(w1 - __uint_as_float(h.y));
        g_Bhi[m][idx] = h;
        g_Blo[m][idx] = l;
    }
}

// ---------------------------------------------------------------------------
// CSR build: zero counts -> histogram -> 3-phase parallel scan -> scatter
// ---------------------------------------------------------------------------
__global__ void hist_zero_kernel() {
    int i = blockIdx.x * blockDim.x + threadIdx.x;
    if (i < NN) g_cnt[i] = 0;
}

__global__ void hist_kernel(const int* __restrict__ dst, int E) {
    int i = blockIdx.x * blockDim.x + threadIdx.x;
    int stride = gridDim.x * blockDim.x;
    for (int e = i; e < E; e += stride) atomicAdd(&g_cnt[dst[e]], 1);
}

// Phase 1: per-block exclusive scan of 256 counts; local prefix -> g_ptr,
// block total -> g_blk.
__global__ __launch_bounds__(256) void scan1_kernel() {
    __shared__ int sh[256];
    int t = threadIdx.x;
    int i = blockIdx.x * 256 + t;
    int v = (i < NN) ? g_cnt[i] : 0;
    sh[t] = v;
    __syncthreads();
    // Hillis-Steele inclusive scan
#pragma unroll
    for (int off = 1; off < 256; off <<= 1) {
        int a = (t >= off) ? sh[t - off] : 0;
        __syncthreads();
        sh[t] += a;
        __syncthreads();
    }
    if (i < NN) g_ptr[i] = sh[t] - v;          // exclusive local prefix
    if (t == 255) g_blk[blockIdx.x] = sh[255]; // block total
}

// Phase 2: single block scans the NB block totals (exclusive).
__global__ __launch_bounds__(512) void scan2_kernel() {
    __shared__ int sh[512];
    int t = threadIdx.x;
    int v = (t < NB) ? g_blk[t] : 0;
    sh[t] = v;
    __syncthreads();
#pragma unroll
    for (int off = 1; off < 512; off <<= 1) {
        int a = (t >= off) ? sh[t - off] : 0;
        __syncthreads();
        sh[t] += a;
        __syncthreads();
    }
    if (t < NB) g_blk[t] = sh[t] - v;          // exclusive block offset
}

// Phase 3: add block offsets; init cursor; set sentinel.
__global__ __launch_bounds__(256) void scan3_kernel(int E) {
    int i = blockIdx.x * 256 + threadIdx.x;
    if (i < NN) {
        int p = g_ptr[i] + g_blk[blockIdx.x];
        g_ptr[i] = p;
        g_cnt[i] = p;   // fill cursor
    }
    if (i == 0) g_ptr[NN] = E;
}

__global__ void scatter_kernel(const int* __restrict__ src,
                               const int* __restrict__ dst, int E) {
    int i = blockIdx.x * blockDim.x + threadIdx.x;
    int stride = gridDim.x * blockDim.x;
    for (int e = i; e < E; e += stride) {
        int pos = atomicAdd(&g_cnt[dst[e]], 1);
        g_ssrc[pos] = src[e];
    }
}

// ---------------------------------------------------------------------------
// Gather kernel: one warp per dst node, quarter-warp (8 lanes) per edge.
// Each lane loads one uint4 (8 halves = 16B) of k and v: a full 128B row per
// 8-lane wavefront, 4 edges in flight per warp (x2 with the manual unroll).
// Head reduction is a single shfl_xor(1): head h = lane pair (2h, 2h+1).
// Epilogue folds the 4 subgroups (shfl_down 16/8), normalizes in-register,
// and stores the final per-node attention output once. NO atomics anywhere.
// ---------------------------------------------------------------------------
__global__ __launch_bounds__(256) void gather_kernel() {
    int gw   = (blockIdx.x * blockDim.x + threadIdx.x) >> 5;
    int lane = threadIdx.x & 31;
    if (gw >= NN) return;
    int start = g_ptr[gw], end = g_ptr[gw + 1];

    int slane = lane & 7;    // dim lane: dims slane*8 .. slane*8+7
    int sg    = lane >> 3;   // edge subgroup 0..3

    // q fragment: 8 halves per lane (all 4 subgroups read the same row)
    uint4 qr = *(const uint4*)(g_qh + (size_t)gw * DIMC + slane * 8);
    float2 q0 = __half22float2(*(__half2*)&qr.x);
    float2 q1 = __half22float2(*(__half2*)&qr.y);
    float2 q2 = __half22float2(*(__half2*)&qr.z);
    float2 q3 = __half22float2(*(__half2*)&qr.w);

    float a0 = 0.f, a1 = 0.f, a2 = 0.f, a3 = 0.f;
    float a4 = 0.f, a5 = 0.f, a6 = 0.f, a7 = 0.f;
    float den = 0.f;   // accumulated at even slane of each head pair

    for (int base = start; base < end; base += 32) {
        int cnt = min(end - base, 32);
        int s_l = (lane < cnt) ? g_ssrc[base + lane] : 0;
        for (int j = 0; j < cnt; j += 8) {
#pragma unroll
            for (int u = 0; u < 2; u++) {
                int  idx   = j + u * 4 + sg;
                bool valid = idx < cnt;
                int  s     = __shfl_sync(0xffffffffu, s_l, idx & 31);

                uint4 kr = *(const uint4*)(g_kh + (size_t)s * DIMC + slane * 8);
                float2 k0 = __half22float2(*(__half2*)&kr.x);
                float2 k1 = __half22float2(*(__half2*)&kr.y);
                float2 k2 = __half22float2(*(__half2*)&kr.z);
                float2 k3 = __half22float2(*(__half2*)&kr.w);
                float p = q0.x * k0.x + q0.y * k0.y + q1.x * k1.x + q1.y * k1.y
                        + q2.x * k2.x + q2.y * k2.y + q3.x * k3.x + q3.y * k3.y;
                p += __shfl_xor_sync(0xffffffffu, p, 1);   // head pair reduce
                float ex = valid ? __expf(p * 0.25f) : 0.f;
                if ((slane & 1) == 0) den += ex;

                uint4 vr = *(const uint4*)(g_vh + (size_t)s * DIMC + slane * 8);
                float2 v0 = __half22float2(*(__half2*)&vr.x);
                float2 v1 = __half22float2(*(__half2*)&vr.y);
                float2 v2 = __half22float2(*(__half2*)&vr.z);
                float2 v3 = __half22float2(*(__half2*)&vr.w);
                a0 += ex * v0.x; a1 += ex * v0.y;
                a2 += ex * v1.x; a3 += ex * v1.y;
                a4 += ex * v2.x; a5 += ex * v2.y;
                a6 += ex * v3.x; a7 += ex * v3.y;
            }
        }
    }

    // fold the 4 subgroups (lanes l, l+8, l+16, l+24)
    a0 += __shfl_down_sync(0xffffffffu, a0, 16); a0 += __shfl_down_sync(0xffffffffu, a0, 8);
    a1 += __shfl_down_sync(0xffffffffu, a1, 16); a1 += __shfl_down_sync(0xffffffffu, a1, 8);
    a2 += __shfl_down_sync(0xffffffffu, a2, 16); a2 += __shfl_down_sync(0xffffffffu, a2, 8);
    a3 += __shfl_down_sync(0xffffffffu, a3, 16); a3 += __shfl_down_sync(0xffffffffu, a3, 8);
    a4 += __shfl_down_sync(0xffffffffu, a4, 16); a4 += __shfl_down_sync(0xffffffffu, a4, 8);
    a5 += __shfl_down_sync(0xffffffffu, a5, 16); a5 += __shfl_down_sync(0xffffffffu, a5, 8);
    a6 += __shfl_down_sync(0xffffffffu, a6, 16); a6 += __shfl_down_sync(0xffffffffu, a6, 8);
    a7 += __shfl_down_sync(0xffffffffu, a7, 16); a7 += __shfl_down_sync(0xffffffffu, a7, 8);
    den += __shfl_down_sync(0xffffffffu, den, 16);
    den += __shfl_down_sync(0xffffffffu, den, 8);

    // per-head denominator from the pair's even lane
    float dh = __shfl_sync(0xffffffffu, den, slane & 6);
    if (lane < 8) {
        float inv = (dh > 0.f) ? (1.f / dh) : 0.f;
        float* op = g_acc + (size_t)gw * DIMC + slane * 8;
        *(float4*)op       = make_float4(a0 * inv, a1 * inv, a2 * inv, a3 * inv);
        *(float4*)(op + 4) = make_float4(a4 * inv, a5 * inv, a6 * inv, a7 * inv);
    }
}

// ---------------------------------------------------------------------------
// Tensor-core GEMM (3xTF32): out[node] = X[node] @ W^T + b, fp32 accuracy.
// ---------------------------------------------------------------------------
__device__ __forceinline__ void mma_tf32(float* c, const unsigned* a,
                                         unsigned b0, unsigned b1) {
    asm volatile(
        "mma.sync.aligned.m16n8k8.row.col.f32.tf32.tf32.f32 "
        "{%0,%1,%2,%3},{%4,%5,%6,%7},{%8,%9},{%0,%1,%2,%3};"
        : "+f"(c[0]), "+f"(c[1]), "+f"(c[2]), "+f"(c[3])
        : "r"(a[0]), "r"(a[1]), "r"(a[2]), "r"(a[3]), "r"(b0), "r"(b1));
}

template <bool OUT_HALF>
__device__ __forceinline__ void gemm_tc(const float* __restrict__ X,
                                        int wsel,
                                        const float* __restrict__ bias,
                                        void* __restrict__ out)
{
    __shared__ float sX[64 * 64];     // 16 KB fp32 tile (later reused for C)
    __shared__ uint2 sBhi[2048];      // 16 KB packed tf32-hi fragments
    __shared__ uint2 sBlo[2048];      // 16 KB packed tf32-lo fragments

    int tid  = threadIdx.x;
    int base = blockIdx.x * 64;

#pragma unroll
    for (int i = 0; i < 8; i++) {
        int idx = tid + i * 256;
        sBhi[idx] = g_Bhi[wsel][idx];
        sBlo[idx] = g_Blo[wsel][idx];
    }

#pragma unroll
    for (int i = 0; i < 4; i++) {
        int idx  = tid + i * 256;
        int row  = idx >> 4;
        int k4   = idx & 15;
        int node = base + row;
        float4 xv = make_float4(0.f, 0.f, 0.f, 0.f);
        if (node < NN) xv = ((const float4*)(X + (size_t)node * DIMC))[k4];
        ((float4*)sX)[row * 16 + (k4 ^ (row & 15))] = xv;
    }
    __syncthreads();

    int lane = tid & 31, warp = tid >> 5;
    int rowg = warp >> 1;
    int colh = warp & 1;
    int gid  = lane >> 2;
    int tig  = lane & 3;
    int r0   = rowg * 16 + gid;
    int r1   = r0 + 8;

    float acc[4][4];
#pragma unroll
    for (int n = 0; n < 4; n++)
#pragma unroll
        for (int j = 0; j < 4; j++) acc[n][j] = 0.f;

#pragma unroll
    for (int ks = 0; ks < 8; ks++) {
        int g0 = 2 * ks;
        int g1 = 2 * ks + 1;
        float a0f = sX[(r0 * 16 + (g0 ^ (r0 & 15))) * 4 + tig];
        float a1f = sX[(r1 * 16 + (g0 ^ (r1 & 15))) * 4 + tig];
        float a2f = sX[(r0 * 16 + (g1 ^ (r0 & 15))) * 4 + tig];
        float a3f = sX[(r1 * 16 + (g1 ^ (r1 & 15))) * 4 + tig];
        unsigned ah[4], al[4];
        ah[0] = f2tf32(a0f); al[0] = f2tf32(a0f - __uint_as_float(ah[0]));
        ah[1] = f2tf32(a1f); al[1] = f2tf32(a1f - __uint_as_float(ah[1]));
        ah[2] = f2tf32(a2f); al[2] = f2tf32(a2f - __uint_as_float(ah[2]));
        ah[3] = f2tf32(a3f); al[3] = f2tf32(a3f - __uint_as_float(ah[3]));
#pragma unroll
        for (int n = 0; n < 4; n++) {
            int nt = colh * 4 + n;
            int bi = (nt * 8 + ks) * 32 + lane;
            uint2 bh = sBhi[bi];
            uint2 bl = sBlo[bi];
            mma_tf32(acc[n], ah, bh.x, bh.y);
            mma_tf32(acc[n], al, bh.x, bh.y);
            mma_tf32(acc[n], ah, bl.x, bl.y);
        }
    }

    __syncthreads();
#pragma unroll
    for (int n = 0; n < 4; n++) {
        int col = (colh * 4 + n) * 8 + 2 * tig;
        int g   = col >> 2;
        int o   = col & 3;
        sX[(r0 * 16 + (g ^ (r0 & 15))) * 4 + o]     = acc[n][0];
        sX[(r0 * 16 + (g ^ (r0 & 15))) * 4 + o + 1] = acc[n][1];
        sX[(r1 * 16 + (g ^ (r1 & 15))) * 4 + o]     = acc[n][2];
        sX[(r1 * 16 + (g ^ (r1 & 15))) * 4 + o + 1] = acc[n][3];
    }
    __syncthreads();

#pragma unroll
    for (int i = 0; i < 4; i++) {
        int idx  = tid + i * 256;
        int row  = idx >> 4;
        int k4   = idx & 15;
        int node = base + row;
        if (node >= NN) continue;
        float4 v  = ((const float4*)sX)[row * 16 + (k4 ^ (row & 15))];
        float4 bb = ((const float4*)bias)[k4];
        v.x += bb.x; v.y += bb.y; v.z += bb.z; v.w += bb.w;
        if (OUT_HALF) {
            __half2 h0 = __float22half2_rn(make_float2(v.x, v.y));
            __half2 h1 = __float22half2_rn(make_float2(v.z, v.w));
            uint2 pk;
            pk.x = *(unsigned*)&h0;
            pk.y = *(unsigned*)&h1;
            *(uint2*)((__half*)out + (size_t)node * DIMC + k4 * 4) = pk;
        } else {
            *(float4*)((float*)out + (size_t)node * DIMC + k4 * 4) = v;
        }
    }
}

__global__ __launch_bounds__(256)
void proj_kernel(const float* __restrict__ query,
                 const float* __restrict__ key,
                 const float* __restrict__ value,
                 const float* __restrict__ bq,
                 const float* __restrict__ bk,
                 const float* __restrict__ bv)
{
    int m = blockIdx.y;
    if (m == 0)      gemm_tc<true>(query, 0, bq, g_qh);
    else if (m == 1) gemm_tc<true>(key,   1, bk, g_kh);
    else             gemm_tc<true>(value, 2, bv, g_vh);
}

__global__ __launch_bounds__(256)
void final_kernel(const float* __restrict__ bo,
                  float* __restrict__ out)
{
    gemm_tc<false>(g_acc, 3, bo, out);
}

// ---------------------------------------------------------------------------
extern "C" void kernel_launch(void* const* d_in, const int* in_sizes, int n_in,
                              void* d_out, int out_size)
{
    const float* query = (const float*)d_in[0];
    const float* key   = (const float*)d_in[1];
    const float* value = (const float*)d_in[2];
    const int*   src   = (const int*)d_in[3];
    const int*   dst   = (const int*)d_in[4];
    const float* Wq = (const float*)d_in[5];  const float* bq = (const float*)d_in[6];
    const float* Wk = (const float*)d_in[7];  const float* bk = (const float*)d_in[8];
    const float* Wv = (const float*)d_in[9];  const float* bv = (const float*)d_in[10];
    const float* Wo = (const float*)d_in[11]; const float* bo = (const float*)d_in[12];
    int E = in_sizes[3];
    if (E > EMAX) E = EMAX;

    pack_kernel<<<4, 256>>>(Wq, Wk, Wv, Wo);

    // CSR build (parallel scan)
    hist_zero_kernel<<<NB, 256>>>();
    hist_kernel<<<1024, 256>>>(dst, E);
    scan1_kernel<<<NB, 256>>>();
    scan2_kernel<<<1, 512>>>();
    scan3_kernel<<<NB, 256>>>(E);
    scatter_kernel<<<1024, 256>>>(src, dst, E);

    // Projections
    dim3 pg((NN + 63) / 64, 3);
    proj_kernel<<<pg, 256>>>(query, key, value, bq, bk, bv);

    // Attention (register-accumulated, atomic-free)
    gather_kernel<<<(NN * 32 + 255) / 256, 256>>>();

    // Output projection
    final_kernel<<<(NN + 63) / 64, 256>>>(bo, (float*)d_out);
}

// round 16
// speedup vs baseline: 1.8676x; 1.0450x over previous
#include <cuda_runtime.h>
#include <cuda_fp16.h>

#define NN   100000
#define DIMC 64
#define HH   4
#define EMAX 1600000
#define NB   ((NN + 255) / 256)   // 391 scan blocks

// Scratch (allocation-free rule: __device__ globals)
__device__ __half g_qh[NN * DIMC];
__device__ __half g_kh[NN * DIMC];
__device__ __half g_vh[NN * DIMC];
__device__ float  g_acc[NN * DIMC];   // normalized attention output (gather)

// CSR scratch
__device__ int g_cnt[NN];         // counts, then fill cursors
__device__ int g_ptr[NN + 1];
__device__ int g_ssrc[EMAX];      // src ids sorted by dst
__device__ int g_blk[NB];         // per-block totals for the scan

// Pre-split, fragment-ordered W images (hi/lo tf32), one per matrix
// (0=Wq, 1=Wk, 2=Wv, 3=Wo). Layout: [(nt*8 + ks)*32 + lane] holds the uint2
// B-fragment {W[c][k0], W[c][k0+4]} with c = nt*8 + lane/4, k0 = ks*8 + lane%4.
__device__ uint2 g_Bhi[4][2048];
__device__ uint2 g_Blo[4][2048];

__device__ __forceinline__ unsigned f2tf32(float x) {
    unsigned r;
    asm("cvt.rna.tf32.f32 %0, %1;" : "=r"(r) : "f"(x));
    return r;
}

// ---------------------------------------------------------------------------
// Pack kernel: split each W into tf32 hi/lo and store in B-fragment order.
// ---------------------------------------------------------------------------
__global__ void pack_kernel(const float* __restrict__ Wq,
                            const float* __restrict__ Wk,
                            const float* __restrict__ Wv,
                            const float* __restrict__ Wo)
{
    int m = blockIdx.x;
    const float* W = (m == 0) ? Wq : (m == 1) ? Wk : (m == 2) ? Wv : Wo;
#pragma unroll
    for (int i = 0; i < 8; i++) {
        int idx  = threadIdx.x + i * 256;     // 0..2047
        int lane = idx & 31;
        int ks   = (idx >> 5) & 7;
        int nt   = idx >> 8;
        int c    = nt * 8 + (lane >> 2);
        int k0   = ks * 8 + (lane & 3);
        float w0 = W[c * DIMC + k0];
        float w1 = W[c * DIMC + k0 + 4];
        uint2 h, l;
        h.x = f2tf32(w0); h.y = f2tf32(w1);
        l.x = f2tf32(w0 - __uint_as_float(h.x));
        l.y = f2tf32(w1 - __uint_as_float(h.y));
        g_Bhi[m][idx] = h;
        g_Blo[m][idx] = l;
    }
}

// ---------------------------------------------------------------------------
// CSR build: zero counts -> histogram -> 3-phase parallel scan -> scatter
// ---------------------------------------------------------------------------
__global__ void hist_zero_kernel() {
    int i = blockIdx.x * blockDim.x + threadIdx.x;
    if (i < NN) g_cnt[i] = 0;
}

__global__ void hist_kernel(const int* __restrict__ dst, int E) {
    int i = blockIdx.x * blockDim.x + threadIdx.x;
    int stride = gridDim.x * blockDim.x;
    for (int e = i; e < E; e += stride) atomicAdd(&g_cnt[dst[e]], 1);
}

// Phase 1: per-block exclusive scan of 256 counts; local prefix -> g_ptr,
// block total -> g_blk.
__global__ __launch_bounds__(256) void scan1_kernel() {
    __shared__ int sh[256];
    int t = threadIdx.x;
    int i = blockIdx.x * 256 + t;
    int v = (i < NN) ? g_cnt[i] : 0;
    sh[t] = v;
    __syncthreads();
    // Hillis-Steele inclusive scan
#pragma unroll
    for (int off = 1; off < 256; off <<= 1) {
        int a = (t >= off) ? sh[t - off] : 0;
        __syncthreads();
        sh[t] += a;
        __syncthreads();
    }
    if (i < NN) g_ptr[i] = sh[t] - v;          // exclusive local prefix
    if (t == 255) g_blk[blockIdx.x] = sh[255]; // block total
}

// Phase 2: single block scans the NB block totals (exclusive).
__global__ __launch_bounds__(512) void scan2_kernel() {
    __shared__ int sh[512];
    int t = threadIdx.x;
    int v = (t < NB) ? g_blk[t] : 0;
    sh[t] = v;
    __syncthreads();
#pragma unroll
    for (int off = 1; off < 512; off <<= 1) {
        int a = (t >= off) ? sh[t - off] : 0;
        __syncthreads();
        sh[t] += a;
        __syncthreads();
    }
    if (t < NB) g_blk[t] = sh[t] - v;          // exclusive block offset
}

// Phase 3: add block offsets; init cursor; set sentinel.
__global__ __launch_bounds__(256) void scan3_kernel(int E) {
    int i = blockIdx.x * 256 + threadIdx.x;
    if (i < NN) {
        int p = g_ptr[i] + g_blk[blockIdx.x];
        g_ptr[i] = p;
        g_cnt[i] = p;   // fill cursor
    }
    if (i == 0) g_ptr[NN] = E;
}

__global__ void scatter_kernel(const int* __restrict__ src,
                               const int* __restrict__ dst, int E) {
    int i = blockIdx.x * blockDim.x + threadIdx.x;
    int stride = gridDim.x * blockDim.x;
    for (int e = i; e < E; e += stride) {
        int pos = atomicAdd(&g_cnt[dst[e]], 1);
        g_ssrc[pos] = src[e];
    }
}

// ---------------------------------------------------------------------------
// Gather kernel: one warp per dst node, quarter-warp (8 lanes) per edge.
// Each lane loads one uint4 (8 halves = 16B) of k and v: a full 128B row per
// 8-lane wavefront, 4 edges in flight per warp (x2 with the manual unroll).
// Head reduction is a single shfl_xor(1): head h = lane pair (2h, 2h+1).
// Epilogue folds the 4 subgroups (shfl_down 16/8), normalizes in-register,
// and stores the final per-node attention output once. NO atomics anywhere.
// ---------------------------------------------------------------------------
__global__ __launch_bounds__(256) void gather_kernel() {
    int gw   = (blockIdx.x * blockDim.x + threadIdx.x) >> 5;
    int lane = threadIdx.x & 31;
    if (gw >= NN) return;
    int start = g_ptr[gw], end = g_ptr[gw + 1];

    int slane = lane & 7;    // dim lane: dims slane*8 .. slane*8+7
    int sg    = lane >> 3;   // edge subgroup 0..3

    // q fragment: 8 halves per lane (all 4 subgroups read the same row)
    uint4 qr = *(const uint4*)(g_qh + (size_t)gw * DIMC + slane * 8);
    float2 q0 = __half22float2(*(__half2*)&qr.x);
    float2 q1 = __half22float2(*(__half2*)&qr.y);
    float2 q2 = __half22float2(*(__half2*)&qr.z);
    float2 q3 = __half22float2(*(__half2*)&qr.w);

    float a0 = 0.f, a1 = 0.f, a2 = 0.f, a3 = 0.f;
    float a4 = 0.f, a5 = 0.f, a6 = 0.f, a7 = 0.f;
    float den = 0.f;   // accumulated at even slane of each head pair

    for (int base = start; base < end; base += 32) {
        int cnt = min(end - base, 32);
        int s_l = (lane < cnt) ? g_ssrc[base + lane] : 0;
        for (int j = 0; j < cnt; j += 8) {
#pragma unroll
            for (int u = 0; u < 2; u++) {
                int  idx   = j + u * 4 + sg;
                bool valid = idx < cnt;
                int  s     = __shfl_sync(0xffffffffu, s_l, idx & 31);

                uint4 kr = *(const uint4*)(g_kh + (size_t)s * DIMC + slane * 8);
                float2 k0 = __half22float2(*(__half2*)&kr.x);
                float2 k1 = __half22float2(*(__half2*)&kr.y);
                float2 k2 = __half22float2(*(__half2*)&kr.z);
                float2 k3 = __half22float2(*(__half2*)&kr.w);
                float p = q0.x * k0.x + q0.y * k0.y + q1.x * k1.x + q1.y * k1.y
                        + q2.x * k2.x + q2.y * k2.y + q3.x * k3.x + q3.y * k3.y;
                p += __shfl_xor_sync(0xffffffffu, p, 1);   // head pair reduce
                float ex = valid ? __expf(p * 0.25f) : 0.f;
                if ((slane & 1) == 0) den += ex;

                uint4 vr = *(const uint4*)(g_vh + (size_t)s * DIMC + slane * 8);
                float2 v0 = __half22float2(*(__half2*)&vr.x);
                float2 v1 = __half22float2(*(__half2*)&vr.y);
                float2 v2 = __half22float2(*(__half2*)&vr.z);
                float2 v3 = __half22float2(*(__half2*)&vr.w);
                a0 += ex * v0.x; a1 += ex * v0.y;
                a2 += ex * v1.x; a3 += ex * v1.y;
                a4 += ex * v2.x; a5 += ex * v2.y;
                a6 += ex * v3.x; a7 += ex * v3.y;
            }
        }
    }

    // fold the 4 subgroups (lanes l, l+8, l+16, l+24)
    a0 += __shfl_down_sync(0xffffffffu, a0, 16); a0 += __shfl_down_sync(0xffffffffu, a0, 8);
    a1 += __shfl_down_sync(0xffffffffu, a1, 16); a1 += __shfl_down_sync(0xffffffffu, a1, 8);
    a2 += __shfl_down_sync(0xffffffffu, a2, 16); a2 += __shfl_down_sync(0xffffffffu, a2, 8);
    a3 += __shfl_down_sync(0xffffffffu, a3, 16); a3 += __shfl_down_sync(0xffffffffu, a3, 8);
    a4 += __shfl_down_sync(0xffffffffu, a4, 16); a4 += __shfl_down_sync(0xffffffffu, a4, 8);
    a5 += __shfl_down_sync(0xffffffffu, a5, 16); a5 += __shfl_down_sync(0xffffffffu, a5, 8);
    a6 += __shfl_down_sync(0xffffffffu, a6, 16); a6 += __shfl_down_sync(0xffffffffu, a6, 8);
    a7 += __shfl_down_sync(0xffffffffu, a7, 16); a7 += __shfl_down_sync(0xffffffffu, a7, 8);
    den += __shfl_down_sync(0xffffffffu, den, 16);
    den += __shfl_down_sync(0xffffffffu, den, 8);

    // per-head denominator from the pair's even lane
    float dh = __shfl_sync(0xffffffffu, den, slane & 6);
    if (lane < 8) {
        float inv = (dh > 0.f) ? (1.f / dh) : 0.f;
        float* op = g_acc + (size_t)gw * DIMC + slane * 8;
        *(float4*)op       = make_float4(a0 * inv, a1 * inv, a2 * inv, a3 * inv);
        *(float4*)(op + 4) = make_float4(a4 * inv, a5 * inv, a6 * inv, a7 * inv);
    }
}

// ---------------------------------------------------------------------------
// Tensor-core GEMM (3xTF32): out[node] = X[node] @ W^T + b, fp32 accuracy.
// ---------------------------------------------------------------------------
__device__ __forceinline__ void mma_tf32(float* c, const unsigned* a,
                                         unsigned b0, unsigned b1) {
    asm volatile(
        "mma.sync.aligned.m16n8k8.row.col.f32.tf32.tf32.f32 "
        "{%0,%1,%2,%3},{%4,%5,%6,%7},{%8,%9},{%0,%1,%2,%3};"
        : "+f"(c[0]), "+f"(c[1]), "+f"(c[2]), "+f"(c[3])
        : "r"(a[0]), "r"(a[1]), "r"(a[2]), "r"(a[3]), "r"(b0), "r"(b1));
}

template <bool OUT_HALF>
__device__ __forceinline__ void gemm_tc(const float* __restrict__ X,
                                        int wsel,
                                        const float* __restrict__ bias,
                                        void* __restrict__ out)
{
    __shared__ float sX[64 * 64];     // 16 KB fp32 tile (later reused for C)
    __shared__ uint2 sBhi[2048];      // 16 KB packed tf32-hi fragments
    __shared__ uint2 sBlo[2048];      // 16 KB packed tf32-lo fragments

    int tid  = threadIdx.x;
    int base = blockIdx.x * 64;

#pragma unroll
    for (int i = 0; i < 8; i++) {
        int idx = tid + i * 256;
        sBhi[idx] = g_Bhi[wsel][idx];
        sBlo[idx] = g_Blo[wsel][idx];
    }

#pragma unroll
    for (int i = 0; i < 4; i++) {
        int idx  = tid + i * 256;
        int row  = idx >> 4;
        int k4   = idx & 15;
        int node = base + row;
        float4 xv = make_float4(0.f, 0.f, 0.f, 0.f);
        if (node < NN) xv = ((const float4*)(X + (size_t)node * DIMC))[k4];
        ((float4*)sX)[row * 16 + (k4 ^ (row & 15))] = xv;
    }
    __syncthreads();

    int lane = tid & 31, warp = tid >> 5;
    int rowg = warp >> 1;
    int colh = warp & 1;
    int gid  = lane >> 2;
    int tig  = lane & 3;
    int r0   = rowg * 16 + gid;
    int r1   = r0 + 8;

    float acc[4][4];
#pragma unroll
    for (int n = 0; n < 4; n++)
#pragma unroll
        for (int j = 0; j < 4; j++) acc[n][j] = 0.f;

#pragma unroll
    for (int ks = 0; ks < 8; ks++) {
        int g0 = 2 * ks;
        int g1 = 2 * ks + 1;
        float a0f = sX[(r0 * 16 + (g0 ^ (r0 & 15))) * 4 + tig];
        float a1f = sX[(r1 * 16 + (g0 ^ (r1 & 15))) * 4 + tig];
        float a2f = sX[(r0 * 16 + (g1 ^ (r0 & 15))) * 4 + tig];
        float a3f = sX[(r1 * 16 + (g1 ^ (r1 & 15))) * 4 + tig];
        unsigned ah[4], al[4];
        ah[0] = f2tf32(a0f); al[0] = f2tf32(a0f - __uint_as_float(ah[0]));
        ah[1] = f2tf32(a1f); al[1] = f2tf32(a1f - __uint_as_float(ah[1]));
        ah[2] = f2tf32(a2f); al[2] = f2tf32(a2f - __uint_as_float(ah[2]));
        ah[3] = f2tf32(a3f); al[3] = f2tf32(a3f - __uint_as_float(ah[3]));
#pragma unroll
        for (int n = 0; n < 4; n++) {
            int nt = colh * 4 + n;
            int bi = (nt * 8 + ks) * 32 + lane;
            uint2 bh = sBhi[bi];
            uint2 bl = sBlo[bi];
            mma_tf32(acc[n], ah, bh.x, bh.y);
            mma_tf32(acc[n], al, bh.x, bh.y);
            mma_tf32(acc[n], ah, bl.x, bl.y);
        }
    }

    __syncthreads();
#pragma unroll
    for (int n = 0; n < 4; n++) {
        int col = (colh * 4 + n) * 8 + 2 * tig;
        int g   = col >> 2;
        int o   = col & 3;
        sX[(r0 * 16 + (g ^ (r0 & 15))) * 4 + o]     = acc[n][0];
        sX[(r0 * 16 + (g ^ (r0 & 15))) * 4 + o + 1] = acc[n][1];
        sX[(r1 * 16 + (g ^ (r1 & 15))) * 4 + o]     = acc[n][2];
        sX[(r1 * 16 + (g ^ (r1 & 15))) * 4 + o + 1] = acc[n][3];
    }
    __syncthreads();

#pragma unroll
    for (int i = 0; i < 4; i++) {
        int idx  = tid + i * 256;
        int row  = idx >> 4;
        int k4   = idx & 15;
        int node = base + row;
        if (node >= NN) continue;
        float4 v  = ((const float4*)sX)[row * 16 + (k4 ^ (row & 15))];
        float4 bb = ((const float4*)bias)[k4];
        v.x += bb.x; v.y += bb.y; v.z += bb.z; v.w += bb.w;
        if (OUT_HALF) {
            __half2 h0 = __float22half2_rn(make_float2(v.x, v.y));
            __half2 h1 = __float22half2_rn(make_float2(v.z, v.w));
            uint2 pk;
            pk.x = *(unsigned*)&h0;
            pk.y = *(unsigned*)&h1;
            *(uint2*)((__half*)out + (size_t)node * DIMC + k4 * 4) = pk;
        } else {
            *(float4*)((float*)out + (size_t)node * DIMC + k4 * 4) = v;
        }
    }
}

__global__ __launch_bounds__(256)
void proj_kernel(const float* __restrict__ query,
                 const float* __restrict__ key,
                 const float* __restrict__ value,
                 const float* __restrict__ bq,
                 const float* __restrict__ bk,
                 const float* __restrict__ bv)
{
    int m = blockIdx.y;
    if (m == 0)      gemm_tc<true>(query, 0, bq, g_qh);
    else if (m == 1) gemm_tc<true>(key,   1, bk, g_kh);
    else             gemm_tc<true>(value, 2, bv, g_vh);
}

__global__ __launch_bounds__(256)
void final_kernel(const float* __restrict__ bo,
                  float* __restrict__ out)
{
    gemm_tc<false>(g_acc, 3, bo, out);
}

// ---------------------------------------------------------------------------
// Launch: CSR build (side stream) runs concurrently with pack+projections
// (main stream); fork/join via events (graph-capture legal). Stream/event
// creation is one-time host-side setup on the first (uncaptured) call and
// changes no device work.
// ---------------------------------------------------------------------------
extern "C" void kernel_launch(void* const* d_in, const int* in_sizes, int n_in,
                              void* d_out, int out_size)
{
    const float* query = (const float*)d_in[0];
    const float* key   = (const float*)d_in[1];
    const float* value = (const float*)d_in[2];
    const int*   src   = (const int*)d_in[3];
    const int*   dst   = (const int*)d_in[4];
    const float* Wq = (const float*)d_in[5];  const float* bq = (const float*)d_in[6];
    const float* Wk = (const float*)d_in[7];  const float* bk = (const float*)d_in[8];
    const float* Wv = (const float*)d_in[9];  const float* bv = (const float*)d_in[10];
    const float* Wo = (const float*)d_in[11]; const float* bo = (const float*)d_in[12];
    int E = in_sizes[3];
    if (E > EMAX) E = EMAX;

    static cudaStream_t s_side = nullptr;
    static cudaEvent_t  ev_fork = nullptr, ev_join = nullptr;
    if (s_side == nullptr) {
        cudaStreamCreateWithFlags(&s_side, cudaStreamNonBlocking);
        cudaEventCreateWithFlags(&ev_fork, cudaEventDisableTiming);
        cudaEventCreateWithFlags(&ev_join, cudaEventDisableTiming);
    }

    // Fork: side stream inherits main-stream ordering
    cudaEventRecord(ev_fork, 0);
    cudaStreamWaitEvent(s_side, ev_fork, 0);

    // Side stream: CSR build (depends only on src/dst)
    hist_zero_kernel<<<NB, 256, 0, s_side>>>();
    hist_kernel<<<1024, 256, 0, s_side>>>(dst, E);
    scan1_kernel<<<NB, 256, 0, s_side>>>();
    scan2_kernel<<<1, 512, 0, s_side>>>();
    scan3_kernel<<<NB, 256, 0, s_side>>>(E);
    scatter_kernel<<<1024, 256, 0, s_side>>>(src, dst, E);
    cudaEventRecord(ev_join, s_side);

    // Main stream: weight pack + projections (independent of CSR)
    pack_kernel<<<4, 256>>>(Wq, Wk, Wv, Wo);
    dim3 pg((NN + 63) / 64, 3);
    proj_kernel<<<pg, 256>>>(query, key, value, bq, bk, bv);

    // Join: gather needs CSR + projections
    cudaStreamWaitEvent(0, ev_join, 0);

    gather_kernel<<<(NN * 32 + 255) / 256, 256>>>();
    final_kernel<<<(NN + 63) / 64, 256>>>(bo, (float*)d_out);
}